// round 1
// baseline (speedup 1.0000x reference)
#include <cuda_runtime.h>

#define NB       1024
#define NITEMS   100000
#define NCL      10
#define DD       64

#define BT       32      // batch rows per CTA (main kernel)
#define TBR      4       // rows per thread
#define TIW      4       // items per thread (adjacent)
#define CHUNK    128     // items per smem tile
#define SPLITS   9       // item-range splits -> grid (32, 9) = 288 CTAs
#define NCHUNK   ((NITEMS + CHUNK - 1) / CHUNK)   // 782

// Scratch (device globals -- no allocation allowed)
__device__ float g_G1[NCL][DD];      // segment-sum of W1 by cluster
__device__ float g_cnt[NCL];         // cluster counts (float)
__device__ float g_H[NB][DD];        // H = input @ G1
__device__ float g_sums[NB][NCL];    // per-(b, cluster) exp-sums

// ---------------------------------------------------------------------------
// Kernel 0: zero scratch (must re-zero every call: deterministic)
// ---------------------------------------------------------------------------
__global__ void kzero() {
    int t = blockIdx.x * blockDim.x + threadIdx.x;
    if (t < NB * NCL)  ((float*)g_sums)[t] = 0.0f;
    if (t < NCL * DD)  ((float*)g_G1)[t]   = 0.0f;
    if (t < NCL)       g_cnt[t]            = 0.0f;
}

// ---------------------------------------------------------------------------
// Kernel 1: G1[c][d] = sum_{i in cluster c} W1[i][d]   and counts.
// 256 threads/block: d = t & 63 (coalesced over W1 row), 4 item-stripes/block.
// Per-thread register accumulators (10-way predicated), global atomic merge.
// ---------------------------------------------------------------------------
__global__ void kG1(const float* __restrict__ W1, const int* __restrict__ cl) {
    int t = threadIdx.x;
    int d = t & 63;
    int stripe   = blockIdx.x * 4 + (t >> 6);
    int nstripes = gridDim.x * 4;

    float acc[NCL];
    float cnt[NCL];
#pragma unroll
    for (int k = 0; k < NCL; k++) { acc[k] = 0.0f; cnt[k] = 0.0f; }

    for (int i = stripe; i < NITEMS; i += nstripes) {
        int   c = cl[i];
        float w = W1[i * DD + d];
#pragma unroll
        for (int k = 0; k < NCL; k++) {
            if (c == k) { acc[k] += w; cnt[k] += 1.0f; }
        }
    }
#pragma unroll
    for (int k = 0; k < NCL; k++) {
        atomicAdd(&g_G1[k][d], acc[k]);
        if (d == 0) atomicAdd(&g_cnt[k], cnt[k]);
    }
}

// ---------------------------------------------------------------------------
// Kernel 2: H[b][d] = sum_c input[b][c] * G1[c][d]    (1024 x 64, trivial)
// ---------------------------------------------------------------------------
__global__ void kH(const float* __restrict__ inp) {
    int t = blockIdx.x * blockDim.x + threadIdx.x;   // 65536 threads
    int b = t >> 6;
    int d = t & 63;
    float a = 0.0f;
#pragma unroll
    for (int c = 0; c < NCL; c++) a += inp[b * NCL + c] * g_G1[c][d];
    g_H[b][d] = a;
}

// ---------------------------------------------------------------------------
// Kernel 3 (main): fused  logits = H @ W2 -> exp -> per-cluster accumulate.
// Grid (32 batch tiles, SPLITS item splits). CTA: 32 rows x streamed chunks.
// Thread: 4 rows x 4 adjacent items, W2 chunk in smem [d][item].
// ---------------------------------------------------------------------------
__global__ void __launch_bounds__(256, 2)
kmain(const float* __restrict__ W2, const int* __restrict__ cl) {
    __shared__ float h_s[BT][DD];          // 8 KB
    __shared__ float w_s[DD][CHUNK];       // 32 KB
    __shared__ int   cl_s[CHUNK];

    int t  = threadIdx.x;
    int tx = t & 31;          // item group: items 4*tx .. 4*tx+3
    int ty = t >> 5;          // warp id -> rows 4*ty .. 4*ty+3
    int r0 = ty * TBR;
    int bbase = blockIdx.x * BT;
    int split = blockIdx.y;

    // stage H tile
    for (int idx = t; idx < BT * DD; idx += 256)
        ((float*)h_s)[idx] = ((const float*)g_H)[bbase * DD + idx];

    float s[TBR][NCL];
#pragma unroll
    for (int rr = 0; rr < TBR; rr++)
#pragma unroll
        for (int k = 0; k < NCL; k++) s[rr][k] = 0.0f;

    for (int ch = split; ch < NCHUNK; ch += SPLITS) {
        int ibase = ch * CHUNK;
        __syncthreads();   // protect w_s/cl_s from previous iteration (and h_s 1st iter)

        // stage W2 chunk: 64 d-rows x 128 items, float4 coalesced
#pragma unroll
        for (int q = 0; q < 8; q++) {
            int idx = t + 256 * q;
            int d   = idx >> 5;
            int c4  = (idx & 31) * 4;
            int gi  = ibase + c4;
            float4 v = make_float4(0.f, 0.f, 0.f, 0.f);
            if (gi < NITEMS)   // NITEMS % 4 == 0, chunk base % 4 == 0 -> full float4 valid
                v = *(const float4*)(W2 + (size_t)d * NITEMS + gi);
            *(float4*)&w_s[d][c4] = v;
        }
        if (t < CHUNK)
            cl_s[t] = (ibase + t < NITEMS) ? cl[ibase + t] : -1;
        __syncthreads();

        // register-tiled GEMM: acc[4 rows][4 items]
        float acc[TBR][TIW];
#pragma unroll
        for (int rr = 0; rr < TBR; rr++)
#pragma unroll
            for (int ii = 0; ii < TIW; ii++) acc[rr][ii] = 0.0f;

#pragma unroll
        for (int d4 = 0; d4 < DD; d4 += 4) {
            float4 hv[TBR];
#pragma unroll
            for (int rr = 0; rr < TBR; rr++)
                hv[rr] = *(const float4*)&h_s[r0 + rr][d4];   // warp-broadcast
#pragma unroll
            for (int dd = 0; dd < 4; dd++) {
                float4 wv = *(const float4*)&w_s[d4 + dd][tx * 4];
#pragma unroll
                for (int rr = 0; rr < TBR; rr++) {
                    float h = ((const float*)&hv[rr])[dd];
                    acc[rr][0] += h * wv.x;
                    acc[rr][1] += h * wv.y;
                    acc[rr][2] += h * wv.z;
                    acc[rr][3] += h * wv.w;
                }
            }
        }

        // exp (no max-subtraction needed: |logit| = O(1)) + segment accumulate
        int cidx[TIW];
#pragma unroll
        for (int ii = 0; ii < TIW; ii++) cidx[ii] = cl_s[tx * 4 + ii];

        float e[TBR][TIW];
#pragma unroll
        for (int rr = 0; rr < TBR; rr++)
#pragma unroll
            for (int ii = 0; ii < TIW; ii++)
                e[rr][ii] = (cidx[ii] >= 0) ? __expf(acc[rr][ii]) : 0.0f;

#pragma unroll
        for (int k = 0; k < NCL; k++)
#pragma unroll
            for (int ii = 0; ii < TIW; ii++) {
                if (cidx[ii] == k) {
#pragma unroll
                    for (int rr = 0; rr < TBR; rr++) s[rr][k] += e[rr][ii];
                }
            }
    }

    // merge: ~40 global red.adds per thread, spread over 10240 addresses
#pragma unroll
    for (int rr = 0; rr < TBR; rr++)
#pragma unroll
        for (int k = 0; k < NCL; k++)
            atomicAdd(&g_sums[bbase + r0 + rr][k], s[rr][k]);
}

// ---------------------------------------------------------------------------
// Kernel 4: finalize  out[b][c] = (S[b][c]/Z_b) / max(count_c, 1)
// ---------------------------------------------------------------------------
__global__ void kfin(float* __restrict__ out) {
    int b = blockIdx.x * blockDim.x + threadIdx.x;
    if (b >= NB) return;
    float v[NCL];
    float z = 0.0f;
#pragma unroll
    for (int c = 0; c < NCL; c++) { v[c] = g_sums[b][c]; z += v[c]; }
    float invz = 1.0f / z;
#pragma unroll
    for (int c = 0; c < NCL; c++)
        out[b * NCL + c] = v[c] * invz / fmaxf(g_cnt[c], 1.0f);
}

// ---------------------------------------------------------------------------
extern "C" void kernel_launch(void* const* d_in, const int* in_sizes, int n_in,
                              void* d_out, int out_size) {
    const float* input = (const float*)d_in[0];   // (1024, 10) f32
    const int*   clust = (const int*)d_in[1];     // (100000,) i32
    const float* W1    = (const float*)d_in[2];   // (100000, 64) f32
    const float* W2    = (const float*)d_in[3];   // (64, 100000) f32
    float*       out   = (float*)d_out;           // (1024, 10) f32

    kzero<<<40, 256>>>();
    kG1<<<64, 256>>>(W1, clust);
    kH<<<256, 256>>>(input);
    dim3 grid(NB / BT, SPLITS);
    kmain<<<grid, 256>>>(W2, clust);
    kfin<<<4, 256>>>(out);
}

// round 2
// speedup vs baseline: 1.1957x; 1.1957x over previous
#include <cuda_runtime.h>

typedef unsigned long long ull;

#define NB      1024
#define NIT     100000
#define NCL     10
#define DD      64
#define CHUNK   128
#define NCHUNK  782          // ceil(100000/128)
#define NP      (NCHUNK*CHUNK)   // 100096 padded items
#define SPLITS  18
#define CPS     44           // ceil(782/18)
#define BT      128          // batch rows per CTA
#define TBR     8            // rows per thread
#define TIW     8            // items per thread
#define NSC     98           // sort CTAs
#define SSPAN   1024

// ------------------------- device scratch (static; no allocation) ----------
__device__ float g_G1[NCL*DD];
__device__ float g_H[NB*DD];
__device__ float g_sums[NB*NCL];
__device__ float g_cntf[NCL];
__device__ int   g_hist[NSC*NCL];
__device__ int   g_base[NSC*NCL];
__device__ int   g_coff[NCL+1];
__device__ int   g_src[NIT];
__device__ float g_W2p[(size_t)DD*NP];   // cluster-sorted, padded W2

// ------------------------- small helpers -----------------------------------
__device__ __forceinline__ void ffma2(ull &d, ull a, ull b) {
    asm("fma.rn.f32x2 %0, %1, %2, %0;" : "+l"(d) : "l"(a), "l"(b));
}
__device__ __forceinline__ ull packdup(float h) {
    ull r; asm("mov.b64 %0, {%1, %1};" : "=l"(r) : "f"(h)); return r;
}
__device__ __forceinline__ void unpack2(ull v, float &x, float &y) {
    asm("mov.b64 {%0, %1}, %2;" : "=f"(x), "=f"(y) : "l"(v));
}

// ------------------------- kzero -------------------------------------------
__global__ void kzero() {
    int t = blockIdx.x * blockDim.x + threadIdx.x;
    if (t < NB*NCL) g_sums[t] = 0.0f;
    if (t < NCL*DD) g_G1[t]   = 0.0f;
}

// ------------------------- sort pass A: per-CTA histogram ------------------
__global__ void khist(const int* __restrict__ cl) {
    __shared__ int h[NCL];
    int t = threadIdx.x;
    if (t < NCL) h[t] = 0;
    __syncthreads();
    int base = blockIdx.x * SSPAN;
    int cnt[NCL];
#pragma unroll
    for (int k = 0; k < NCL; k++) cnt[k] = 0;
#pragma unroll
    for (int q = 0; q < 4; q++) {
        int i = base + q*256 + t;
        if (i < NIT) {
            int c = cl[i];
#pragma unroll
            for (int k = 0; k < NCL; k++) if (c == k) cnt[k]++;
        }
    }
#pragma unroll
    for (int k = 0; k < NCL; k++) if (cnt[k]) atomicAdd(&h[k], cnt[k]);
    __syncthreads();
    if (t < NCL) g_hist[blockIdx.x*NCL + t] = h[t];
}

// ------------------------- sort pass B: scan (1 block) ---------------------
__global__ void kscan() {
    __shared__ int tot[NCL], off[NCL+1];
    int t = threadIdx.x;
    if (t < NCL) {
        int s = 0;
        for (int b = 0; b < NSC; b++) s += g_hist[b*NCL + t];
        tot[t] = s;
        g_cntf[t] = (float)s;
    }
    __syncthreads();
    if (t == 0) {
        int r = 0;
        for (int c = 0; c < NCL; c++) { off[c] = r; g_coff[c] = r; r += tot[c]; }
        off[NCL] = r; g_coff[NCL] = r;
    }
    __syncthreads();
    if (t < NCL) {
        int run = off[t];
        for (int b = 0; b < NSC; b++) {
            g_base[b*NCL + t] = run;
            run += g_hist[b*NCL + t];
        }
    }
}

// ------------------------- sort pass C: deterministic rank+scatter ---------
__global__ void kscatter(const int* __restrict__ cl) {
    __shared__ int run[NCL];
    __shared__ int wc[8][NCL];
    int t = threadIdx.x, lane = t & 31, w = t >> 5;
    if (t < NCL) run[t] = g_base[blockIdx.x*NCL + t];
    __syncthreads();
    unsigned ltm = (1u << lane) - 1u;
    int base = blockIdx.x * SSPAN;
    for (int q = 0; q < 4; q++) {
        int i = base + q*256 + t;
        int c = (i < NIT) ? cl[i] : -1;
        int myrank = 0;
#pragma unroll
        for (int k = 0; k < NCL; k++) {
            unsigned b = __ballot_sync(0xffffffffu, c == k);
            if (c == k) myrank = __popc(b & ltm);
            if (lane == 0) wc[w][k] = __popc(b);
        }
        __syncthreads();
        if (t < NCL) {
            int k = t, s = run[k];
            for (int ww = 0; ww < 8; ww++) { int tmp = wc[ww][k]; wc[ww][k] = s; s += tmp; }
            run[k] = s;
        }
        __syncthreads();
        if (c >= 0) g_src[wc[w][c] + myrank] = i;
        __syncthreads();
    }
}

// ------------------------- physical permute of W2 --------------------------
__global__ void kpermW2(const float* __restrict__ W2) {
    int pos = blockIdx.x * 256 + threadIdx.x;
    if (pos >= NP) return;
    if (pos < NIT) {
        int src = g_src[pos];
#pragma unroll 8
        for (int d = 0; d < DD; d++)
            g_W2p[(size_t)d*NP + pos] = __ldg(&W2[(size_t)d*NIT + src]);
    } else {
#pragma unroll 8
        for (int d = 0; d < DD; d++)
            g_W2p[(size_t)d*NP + pos] = 0.0f;
    }
}

// ------------------------- G1 = segment-sum of W1 --------------------------
__global__ void kG1(const float* __restrict__ W1, const int* __restrict__ cl) {
    int t = threadIdx.x, d = t & 63;
    int stripe = blockIdx.x*4 + (t >> 6), ns = gridDim.x*4;
    float acc[NCL];
#pragma unroll
    for (int k = 0; k < NCL; k++) acc[k] = 0.0f;
    for (int i = stripe; i < NIT; i += ns) {
        int c = cl[i];
        float w = W1[i*DD + d];
#pragma unroll
        for (int k = 0; k < NCL; k++) if (c == k) acc[k] += w;
    }
#pragma unroll
    for (int k = 0; k < NCL; k++) atomicAdd(&g_G1[k*DD + d], acc[k]);
}

// ------------------------- H = input @ G1 ----------------------------------
__global__ void kH(const float* __restrict__ inp) {
    int t = blockIdx.x * blockDim.x + threadIdx.x;
    int b = t >> 6, d = t & 63;
    float a = 0.0f;
#pragma unroll
    for (int c = 0; c < NCL; c++) a += inp[b*NCL + c] * g_G1[c*DD + d];
    g_H[b*DD + d] = a;
}

// ------------------------- main fused kernel -------------------------------
// thread map: tx = t&15 (item group: items 8*tx..8*tx+7 of chunk)
//             ty = t>>4 (row group: rows 8*ty..8*ty+7 of the 128-row tile)
__device__ __forceinline__ void stage_w(float* wbase, int buf, int ch, int t) {
    float* dst = wbase + buf * 8192;
    int ibase = ch * CHUNK;
#pragma unroll
    for (int q = 0; q < 8; q++) {
        int j = t + q*256;                  // float4 index in chunk (0..2047)
        int d = j >> 5, f = j & 31;
        int slot = (f >> 1) | ((f & 1) << 4);   // de-interleave halves
        const float* gp = g_W2p + (size_t)d*NP + ibase + f*4;
        unsigned sa = (unsigned)__cvta_generic_to_shared(dst + d*128 + slot*4);
        asm volatile("cp.async.cg.shared.global [%0], [%1], 16;" :: "r"(sa), "l"(gp));
    }
}

__device__ __forceinline__ void flush_s(int c, float* s0, float* s1, int rowbase) {
#pragma unroll
    for (int rr = 0; rr < TBR; rr++) {
        atomicAdd(&g_sums[(rowbase + rr)*NCL + c], s0[rr]);
        if (c + 1 < NCL) atomicAdd(&g_sums[(rowbase + rr)*NCL + c + 1], s1[rr]);
        s0[rr] = 0.0f; s1[rr] = 0.0f;
    }
}

__global__ void __launch_bounds__(256, 1) kmain() {
    extern __shared__ float smem[];
    float* h_s = smem;               // 8192 floats (swizzled)
    float* w_s = smem + 8192;        // 2 x 8192 floats
    __shared__ int coff_s[NCL+1];

    int t  = threadIdx.x;
    int tx = t & 15;
    int ty = t >> 4;
    int r0 = ty * TBR;
    int bbase = blockIdx.x * BT;
    int ch_lo = blockIdx.y * CPS;
    int ch_hi = min(ch_lo + CPS, NCHUNK);

    if (t < NCL+1) coff_s[t] = g_coff[t];

    // stage H tile with XOR-16-float swizzle on (row & 8)
    for (int idx = t; idx < BT*DD; idx += 256) {
        int row = idx >> 6, d = idx & 63;
        h_s[row*64 + (d ^ ((row & 8) ? 16 : 0))] = g_H[(bbase + row)*DD + d];
    }
    stage_w(w_s, 0, ch_lo, t);
    asm volatile("cp.async.commit_group;");
    __syncthreads();

    int cur = 0;
    { int ib = ch_lo * CHUNK; while (coff_s[cur+1] <= ib) cur++; }

    float s0[TBR], s1[TBR];
#pragma unroll
    for (int rr = 0; rr < TBR; rr++) { s0[rr] = 0.0f; s1[rr] = 0.0f; }

    int rowbase = bbase + r0;
    int n = ch_hi - ch_lo;

    for (int i = 0; i < n; i++) {
        int ch = ch_lo + i;
        int buf = i & 1;
        if (i + 1 < n) stage_w(w_s, buf ^ 1, ch + 1, t);
        asm volatile("cp.async.commit_group;");
        asm volatile("cp.async.wait_group 1;" ::: "memory");
        __syncthreads();

        int ibase = ch * CHUNK;
        int nc = cur;
        while (coff_s[nc+1] <= ibase) nc++;
        if (nc != cur) { flush_s(cur, s0, s1, rowbase); cur = nc; }
        int bpos = coff_s[cur+1];

        const float* wb = w_s + buf * 8192;

        ull acc[TBR][4];
#pragma unroll
        for (int rr = 0; rr < TBR; rr++)
#pragma unroll
            for (int j = 0; j < 4; j++) acc[rr][j] = 0ULL;

#pragma unroll 2
        for (int d4 = 0; d4 < DD; d4 += 4) {
            float4 hv[TBR];
#pragma unroll
            for (int rr = 0; rr < TBR; rr++) {
                int row = r0 + rr;
                hv[rr] = *(const float4*)(h_s + row*64 + (d4 ^ ((row & 8) ? 16 : 0)));
            }
#pragma unroll
            for (int dd = 0; dd < 4; dd++) {
                const ull* wp = (const ull*)(wb + (d4 + dd)*128 + tx*4);
                ull w0 = wp[0], w1 = wp[1];
                ull w2 = wp[32], w3 = wp[33];
#pragma unroll
                for (int rr = 0; rr < TBR; rr++) {
                    float h = ((const float*)&hv[rr])[dd];
                    ull hh = packdup(h);
                    ffma2(acc[rr][0], w0, hh);
                    ffma2(acc[rr][1], w1, hh);
                    ffma2(acc[rr][2], w2, hh);
                    ffma2(acc[rr][3], w3, hh);
                }
            }
        }

        // epilogue: exp + 2-slot segment accumulate (items sorted by cluster)
        int pb = ibase + tx*8;
#pragma unroll
        for (int rr = 0; rr < TBR; rr++) {
#pragma unroll
            for (int j = 0; j < 4; j++) {
                float x0, x1;
                unpack2(acc[rr][j], x0, x1);
                float e0 = __expf(x0), e1 = __expf(x1);
                int p = pb + 2*j;
                if (p < bpos)          s0[rr] += e0;
                else if (p < NIT)      s1[rr] += e0;
                if (p + 1 < bpos)      s0[rr] += e1;
                else if (p + 1 < NIT)  s1[rr] += e1;
            }
        }
        __syncthreads();   // all warps done with buf before it is overwritten
    }
    flush_s(cur, s0, s1, rowbase);
}

// ------------------------- finalize ----------------------------------------
__global__ void kfin(float* __restrict__ out) {
    int b = blockIdx.x * blockDim.x + threadIdx.x;
    if (b >= NB) return;
    float v[NCL];
    float z = 0.0f;
#pragma unroll
    for (int c = 0; c < NCL; c++) { v[c] = g_sums[b*NCL + c]; z += v[c]; }
    float invz = 1.0f / z;
#pragma unroll
    for (int c = 0; c < NCL; c++)
        out[b*NCL + c] = v[c] * invz / fmaxf(g_cntf[c], 1.0f);
}

// ---------------------------------------------------------------------------
extern "C" void kernel_launch(void* const* d_in, const int* in_sizes, int n_in,
                              void* d_out, int out_size) {
    const float* input = (const float*)d_in[0];   // (1024, 10) f32
    const int*   clust = (const int*)d_in[1];     // (100000,) i32
    const float* W1    = (const float*)d_in[2];   // (100000, 64) f32
    const float* W2    = (const float*)d_in[3];   // (64, 100000) f32
    float*       out   = (float*)d_out;           // (1024, 10) f32

    cudaFuncSetAttribute(kmain, cudaFuncAttributeMaxDynamicSharedMemorySize, 98304);

    kzero<<<44, 256>>>();
    khist<<<NSC, 256>>>(clust);
    kG1<<<128, 256>>>(W1, clust);
    kscan<<<1, 32>>>();
    kscatter<<<NSC, 256>>>(clust);
    kpermW2<<<(NP + 255)/256, 256>>>(W2);
    kH<<<256, 256>>>(input);
    dim3 grid(NB / BT, SPLITS);
    kmain<<<grid, 256, 98304>>>();
    kfin<<<4, 256>>>(out);
}

// round 4
// speedup vs baseline: 2.9306x; 2.4509x over previous
#include <cuda_runtime.h>
#include <cuda_bf16.h>
#include <cstdint>

typedef unsigned int uint;

#define NB      1024
#define NIT     100000
#define NCL     10
#define DD      64
#define CH      128                  // items per chunk
#define NCH     782                  // NP / CH
#define NP      (NCH*CH)             // 100096
#define NS      18                   // item splits
#define CPS     44                   // chunks per CTA (ceil 782/18)
#define BT      128                  // batch rows per CTA
#define NSC     98                   // sort CTAs
#define SSPAN   1024
#define LOG2E   1.4426950408889634f

// smem layout for kmain (relative to 1024-aligned base)
#define SM_AH   0
#define SM_AL   16384
#define SM_B0   32768                // buffer b at SM_B0 + b*32768; Bl at +16384
#define SMEM_KM (98304 + 1024)

// ---------------- device scratch ----------------
__device__ float  g_G1[NCL*DD];
__device__ float  g_sums[NB*NCL];
__device__ float  g_cntf[NCL];
__device__ int    g_hist[NSC*NCL];
__device__ int    g_base[NSC*NCL];
__device__ int    g_coff[NCL+1];
__device__ int    g_dst[NIT];
__device__ __align__(16) unsigned short g_Hh[NB*DD];
__device__ __align__(16) unsigned short g_Hl[NB*DD];
__device__ __align__(16) unsigned short g_W2h[(size_t)NP*DD];
__device__ __align__(16) unsigned short g_W2l[(size_t)NP*DD];

// ---------------- PTX helpers (baseline ISA only: sm_80-class) --------------
__device__ __forceinline__ uint32_t smem_u32(const void* p) {
    uint32_t a;
    asm("{ .reg .u64 t; cvta.to.shared.u64 t, %1; cvt.u32.u64 %0, t; }" : "=r"(a) : "l"(p));
    return a;
}
__device__ __forceinline__ float ex2f(float x) {
    float r; asm("ex2.approx.ftz.f32 %0, %1;" : "=f"(r) : "f"(x)); return r;
}
#define SW128(o) ((o) ^ (((o) >> 3) & 0x70))

__device__ __forceinline__ void cpa16(uint32_t dst, const void* src) {
    asm volatile("cp.async.cg.shared.global [%0], [%1], 16;" :: "r"(dst), "l"(src));
}
#define CPA_COMMIT() asm volatile("cp.async.commit_group;")
#define CPA_WAIT0()  asm volatile("cp.async.wait_group 0;" ::: "memory")
#define CPA_WAIT1()  asm volatile("cp.async.wait_group 1;" ::: "memory")

#define LDSM4(R, A) \
    asm volatile("ldmatrix.sync.aligned.m8n8.x4.shared.b16 {%0,%1,%2,%3}, [%4];" \
        : "=r"((R)[0]), "=r"((R)[1]), "=r"((R)[2]), "=r"((R)[3]) : "r"(A))

__device__ __forceinline__ void mma_bf16(float* c, const uint* a, uint b0, uint b1) {
    asm volatile("mma.sync.aligned.m16n8k16.row.col.f32.bf16.bf16.f32 "
        "{%0,%1,%2,%3}, {%4,%5,%6,%7}, {%8,%9}, {%0,%1,%2,%3};"
        : "+f"(c[0]), "+f"(c[1]), "+f"(c[2]), "+f"(c[3])
        : "r"(a[0]), "r"(a[1]), "r"(a[2]), "r"(a[3]), "r"(b0), "r"(b1));
}

// ---------------- kzero ----------------
__global__ void kzero() {
    int t = blockIdx.x * blockDim.x + threadIdx.x;
    if (t < NB*NCL) g_sums[t] = 0.0f;
    if (t < NCL*DD) g_G1[t]   = 0.0f;
    if (t < (NP-NIT)*DD) {                        // zero padding rows
        g_W2h[(size_t)NIT*DD + t] = 0;
        g_W2l[(size_t)NIT*DD + t] = 0;
    }
}

// ---------------- histogram ----------------
__global__ void khist(const int* __restrict__ cl) {
    __shared__ int h[NCL];
    int t = threadIdx.x;
    if (t < NCL) h[t] = 0;
    __syncthreads();
    int base = blockIdx.x * SSPAN;
    int cnt[NCL];
#pragma unroll
    for (int k = 0; k < NCL; k++) cnt[k] = 0;
#pragma unroll
    for (int q = 0; q < 4; q++) {
        int i = base + q*256 + t;
        if (i < NIT) {
            int c = cl[i];
#pragma unroll
            for (int k = 0; k < NCL; k++) if (c == k) cnt[k]++;
        }
    }
#pragma unroll
    for (int k = 0; k < NCL; k++) if (cnt[k]) atomicAdd(&h[k], cnt[k]);
    __syncthreads();
    if (t < NCL) g_hist[blockIdx.x*NCL + t] = h[t];
}

// ---------------- scan (warp per cluster) ----------------
__global__ void kscan() {
    __shared__ int tot[NCL], off[NCL+1];
    int t = threadIdx.x, c = t >> 5, lane = t & 31;
    if (c < NCL) {
        int s = 0;
        for (int b = lane; b < NSC; b += 32) s += g_hist[b*NCL + c];
#pragma unroll
        for (int o = 16; o; o >>= 1) s += __shfl_xor_sync(~0u, s, o);
        if (!lane) { tot[c] = s; g_cntf[c] = (float)s; }
    }
    __syncthreads();
    if (t == 0) {
        int r = 0;
        for (int k = 0; k < NCL; k++) { off[k] = r; g_coff[k] = r; r += tot[k]; }
        off[NCL] = r; g_coff[NCL] = r;
    }
    __syncthreads();
    if (c < NCL) {
        int carry = off[c];
        for (int b0 = 0; b0 < NSC; b0 += 32) {
            int b = b0 + lane;
            int v = (b < NSC) ? g_hist[b*NCL + c] : 0;
            int x = v;
#pragma unroll
            for (int o = 1; o < 32; o <<= 1) {
                int y = __shfl_up_sync(~0u, x, o);
                if (lane >= o) x += y;
            }
            if (b < NSC) g_base[b*NCL + c] = carry + x - v;
            carry += __shfl_sync(~0u, x, 31);
        }
    }
}

// ---------------- rank + destination index ----------------
__global__ void kscatter(const int* __restrict__ cl) {
    __shared__ int run[NCL];
    __shared__ int wc[8][NCL];
    int t = threadIdx.x, lane = t & 31, w = t >> 5;
    if (t < NCL) run[t] = g_base[blockIdx.x*NCL + t];
    __syncthreads();
    unsigned ltm = (1u << lane) - 1u;
    int base = blockIdx.x * SSPAN;
    for (int q = 0; q < 4; q++) {
        int i = base + q*256 + t;
        int c = (i < NIT) ? cl[i] : -1;
        int myrank = 0;
#pragma unroll
        for (int k = 0; k < NCL; k++) {
            unsigned b = __ballot_sync(0xffffffffu, c == k);
            if (c == k) myrank = __popc(b & ltm);
            if (lane == 0) wc[w][k] = __popc(b);
        }
        __syncthreads();
        if (t < NCL) {
            int k = t, s = run[k];
            for (int ww = 0; ww < 8; ww++) { int tmp = wc[ww][k]; wc[ww][k] = s; s += tmp; }
            run[k] = s;
        }
        __syncthreads();
        if (c >= 0) g_dst[i] = wc[w][c] + myrank;
        __syncthreads();
    }
}

// ---------------- W2 permute + transpose + bf16 split ----------------------
// dst: row-major [pos, 64] bf16 hi/lo, 128B rows (n-major / "col" operand layout)
#define PITCH 264
__global__ void kperm(const float* __restrict__ W2) {
    extern __shared__ unsigned short sh[];
    unsigned short* shh = sh;
    unsigned short* shl = sh + DD*PITCH;
    int t = threadIdx.x;
    int i  = blockIdx.x * 256 + t;
#pragma unroll 8
    for (int d = 0; d < DD; d++) {
        float x = (i < NIT) ? W2[(size_t)d*NIT + i] : 0.0f;
        __nv_bfloat16 h = __float2bfloat16(x);
        float rem = x - __bfloat162float(h);
        shh[d*PITCH + t] = __bfloat16_as_ushort(h);
        shl[d*PITCH + t] = __bfloat16_as_ushort(__float2bfloat16(rem));
    }
    __syncthreads();
    if (i >= NIT) return;
    int dp = g_dst[i];
    uint v[32];
#pragma unroll
    for (int j = 0; j < 32; j++)
        v[j] = (uint)shh[(2*j)*PITCH + t] | ((uint)shh[(2*j+1)*PITCH + t] << 16);
    uint4* dh = (uint4*)(g_W2h + (size_t)dp*DD);
#pragma unroll
    for (int q = 0; q < 8; q++) dh[q] = make_uint4(v[4*q], v[4*q+1], v[4*q+2], v[4*q+3]);
#pragma unroll
    for (int j = 0; j < 32; j++)
        v[j] = (uint)shl[(2*j)*PITCH + t] | ((uint)shl[(2*j+1)*PITCH + t] << 16);
    uint4* dl = (uint4*)(g_W2l + (size_t)dp*DD);
#pragma unroll
    for (int q = 0; q < 8; q++) dl[q] = make_uint4(v[4*q], v[4*q+1], v[4*q+2], v[4*q+3]);
}

// ---------------- G1 = segment-sum of W1 ----------------
__global__ void kG1(const float* __restrict__ W1, const int* __restrict__ cl) {
    int t = threadIdx.x, d = t & 63;
    int stripe = blockIdx.x*4 + (t >> 6), ns = gridDim.x*4;
    float acc[NCL];
#pragma unroll
    for (int k = 0; k < NCL; k++) acc[k] = 0.0f;
    for (int i = stripe; i < NIT; i += ns) {
        int c = cl[i];
        float w = W1[i*DD + d];
#pragma unroll
        for (int k = 0; k < NCL; k++) if (c == k) acc[k] += w;
    }
#pragma unroll
    for (int k = 0; k < NCL; k++) atomicAdd(&g_G1[k*DD + d], acc[k]);
}

// ---------------- H = (input @ G1) * log2e, bf16 split ----------------
__global__ void kH(const float* __restrict__ inp) {
    int t = blockIdx.x * blockDim.x + threadIdx.x;
    int b = t >> 6, d = t & 63;
    float a = 0.0f;
#pragma unroll
    for (int c = 0; c < NCL; c++) a += inp[b*NCL + c] * g_G1[c*DD + d];
    a *= LOG2E;
    __nv_bfloat16 h = __float2bfloat16(a);
    float rem = a - __bfloat162float(h);
    g_Hh[b*DD + d] = __bfloat16_as_ushort(h);
    g_Hl[b*DD + d] = __bfloat16_as_ushort(__float2bfloat16(rem));
}

// ---------------- main: HMMA (mma.sync) GEMM + fused exp/segment epilogue --
__device__ __forceinline__ void stage_B(uint32_t sb, int buf, int ch, int t) {
    uint32_t bh = sb + SM_B0 + buf*32768;
    const char* gh = (const char*)g_W2h + (size_t)ch*CH*128;
    const char* gl = (const char*)g_W2l + (size_t)ch*CH*128;
#pragma unroll
    for (int q = 0; q < 4; q++) {
        int off = (t + q*256) * 16;
        int so  = SW128(off);
        cpa16(bh + so,         gh + off);
        cpa16(bh + 16384 + so, gl + off);
    }
}

__global__ void __launch_bounds__(256, 1) kmain() {
    extern __shared__ char dsm[];
    __shared__ int coff_s[NCL+1];
    uint32_t sb = (smem_u32(dsm) + 1023u) & ~1023u;

    int t = threadIdx.x, lane = t & 31, w = t >> 5;
    int bbase = blockIdx.x * BT;
    int ch_lo = blockIdx.y * CPS;
    int ch_hi = min(ch_lo + CPS, NCH);
    int n = ch_hi - ch_lo;

    if (t < NCL+1) coff_s[t] = g_coff[t];

    // stage A (Hh/Hl, 16 KB each, SW128) + first B chunk
    {
        const char* gh = (const char*)g_Hh + (size_t)bbase*128;
        const char* gl = (const char*)g_Hl + (size_t)bbase*128;
#pragma unroll
        for (int q = 0; q < 4; q++) {
            int off = (t + q*256) * 16;
            int so  = SW128(off);
            cpa16(sb + SM_AH + so, gh + off);
            cpa16(sb + SM_AL + so, gl + off);
        }
    }
    stage_B(sb, 0, ch_lo, t);
    CPA_COMMIT();
    CPA_WAIT0();
    __syncthreads();

    // ---- per-lane ldmatrix address precompute ----
    int m  = lane >> 3, rl = lane & 7;
    int rowb = ((m >> 1) << 3) + rl;     // B: matrix row within 16-item pair
    int kadd = m & 1;                    // B: k-unit select
    int bx[4];
#pragma unroll
    for (int ks = 0; ks < 4; ks++)
        bx[ks] = rowb*128 + ((ks*32 + kadd*16) ^ (rl*16));

    // ---- load A fragments (resident for whole kernel) ----
    uint ah[4][4], al[4][4];
    {
        int arow = w*16 + ((lane >> 3) & 1)*8 + rl;
#pragma unroll
        for (int ks = 0; ks < 4; ks++) {
            int au   = ks*2 + (lane >> 4);
            int aoff = arow*128 + ((au*16) ^ (rl*16));
            LDSM4(ah[ks], sb + SM_AH + aoff);
            LDSM4(al[ks], sb + SM_AL + aoff);
        }
    }

    // ---- epilogue state ----
    int row0 = bbase + w*16 + (lane >> 2);
    int row1 = row0 + 8;
    int qd   = (lane & 3) * 2;
    float s0a = 0.f, s0b = 0.f, s1a = 0.f, s1b = 0.f;
    int cur = 0;
    { int ib = ch_lo * CH; while (coff_s[cur+1] <= ib) cur++; }

    for (int ii = 0; ii < n; ii++) {
        int buf = ii & 1;
        if (ii + 1 < n) { stage_B(sb, buf ^ 1, ch_lo + ii + 1, t); CPA_COMMIT(); CPA_WAIT1(); }
        else            { CPA_WAIT0(); }
        __syncthreads();

        uint32_t bbh = sb + SM_B0 + buf*32768;

        float acc[16][4];
#pragma unroll
        for (int nt = 0; nt < 16; nt++)
#pragma unroll
            for (int j = 0; j < 4; j++) acc[nt][j] = 0.0f;

#pragma unroll
        for (int ntp = 0; ntp < 8; ntp++) {
#pragma unroll
            for (int ks = 0; ks < 4; ks++) {
                uint32_t a0 = bbh + ntp*2048 + bx[ks];
                uint r[4], q[4];
                LDSM4(r, a0);             // Bh: r0,r1 = tile 2ntp; r2,r3 = tile 2ntp+1
                LDSM4(q, a0 + 16384);     // Bl
                mma_bf16(acc[2*ntp],   ah[ks], r[0], r[1]);
                mma_bf16(acc[2*ntp],   ah[ks], q[0], q[1]);
                mma_bf16(acc[2*ntp],   al[ks], r[0], r[1]);
                mma_bf16(acc[2*ntp+1], ah[ks], r[2], r[3]);
                mma_bf16(acc[2*ntp+1], ah[ks], q[2], q[3]);
                mma_bf16(acc[2*ntp+1], al[ks], r[2], r[3]);
            }
        }

        // ---- epilogue: exp2 + sorted 2-slot segment accumulate ----
        int ibase = (ch_lo + ii) * CH;
        {
            int nc = cur;
            while (coff_s[nc+1] <= ibase) nc++;
            if (nc != cur) {
                atomicAdd(&g_sums[row0*NCL + cur], s0a);
                atomicAdd(&g_sums[row1*NCL + cur], s0b);
                if (cur + 1 < NCL) {
                    atomicAdd(&g_sums[row0*NCL + cur + 1], s1a);
                    atomicAdd(&g_sums[row1*NCL + cur + 1], s1b);
                }
                s0a = s0b = s1a = s1b = 0.f;
                cur = nc;
            }
        }
        int bpos = coff_s[cur+1];

#pragma unroll
        for (int nt = 0; nt < 16; nt++) {
            float e0 = ex2f(acc[nt][0]);
            float e1 = ex2f(acc[nt][1]);
            float e2 = ex2f(acc[nt][2]);
            float e3 = ex2f(acc[nt][3]);
            int p0 = ibase + nt*8 + qd;
            if (p0 < bpos)          { s0a += e0; s0b += e2; }
            else if (p0 < NIT)      { s1a += e0; s1b += e2; }
            if (p0 + 1 < bpos)      { s0a += e1; s0b += e3; }
            else if (p0 + 1 < NIT)  { s1a += e1; s1b += e3; }
        }
        __syncthreads();
    }

    atomicAdd(&g_sums[row0*NCL + cur], s0a);
    atomicAdd(&g_sums[row1*NCL + cur], s0b);
    if (cur + 1 < NCL) {
        atomicAdd(&g_sums[row0*NCL + cur + 1], s1a);
        atomicAdd(&g_sums[row1*NCL + cur + 1], s1b);
    }
}

// ---------------- finalize ----------------
__global__ void kfin(float* __restrict__ out) {
    int b = blockIdx.x * blockDim.x + threadIdx.x;
    if (b >= NB) return;
    float v[NCL], z = 0.0f;
#pragma unroll
    for (int c = 0; c < NCL; c++) { v[c] = g_sums[b*NCL + c]; z += v[c]; }
    float invz = 1.0f / z;
#pragma unroll
    for (int c = 0; c < NCL; c++)
        out[b*NCL + c] = v[c] * invz / fmaxf(g_cntf[c], 1.0f);
}

// ---------------------------------------------------------------------------
extern "C" void kernel_launch(void* const* d_in, const int* in_sizes, int n_in,
                              void* d_out, int out_size) {
    const float* input = (const float*)d_in[0];   // (1024, 10) f32
    const int*   clust = (const int*)d_in[1];     // (100000,) i32
    const float* W1    = (const float*)d_in[2];   // (100000, 64) f32
    const float* W2    = (const float*)d_in[3];   // (64, 100000) f32
    float*       out   = (float*)d_out;           // (1024, 10) f32

    cudaFuncSetAttribute(kmain, cudaFuncAttributeMaxDynamicSharedMemorySize, SMEM_KM);
    cudaFuncSetAttribute(kperm, cudaFuncAttributeMaxDynamicSharedMemorySize, 2*DD*PITCH*2);

    kzero<<<40, 256>>>();
    khist<<<NSC, 256>>>(clust);
    kG1<<<128, 256>>>(W1, clust);
    kscan<<<1, 320>>>();
    kscatter<<<NSC, 256>>>(clust);
    kperm<<<391, 256, 2*DD*PITCH*2>>>(W2);
    kH<<<256, 256>>>(input);
    dim3 grid(NB / BT, NS);
    kmain<<<grid, 256, SMEM_KM>>>();
    kfin<<<4, 256>>>(out);
}

// round 5
// speedup vs baseline: 3.7220x; 1.2701x over previous
#include <cuda_runtime.h>
#include <cuda_bf16.h>
#include <cstdint>

typedef unsigned int uint;

#define NB      1024
#define NIT     100000
#define NCL     10
#define DD      64
#define CH      128                  // items per chunk
#define NCH     782                  // NP / CH
#define NP      (NCH*CH)             // 100096
#define NS      18                   // item splits
#define CPS     44                   // chunks per CTA
#define BT      128                  // batch rows per CTA
#define NSC     98                   // sort CTAs
#define SSPAN   1024
#define LOG2E   1.4426950408889634f

// kmain smem (relative to 1024-aligned base): Ah@0 Al@16K | B0@32K B1@48K
#define SM_AH   0
#define SM_AL   16384
#define SM_B0   32768
#define SMEM_KM (65536 + 1024)

// ---------------- device scratch (zero at load; kfin restores zeros) -------
__device__ float  g_G1[NCL*DD];
__device__ float  g_sums[NB*NCL];
__device__ float  g_cntf[NCL];
__device__ int    g_hist[NSC*NCL];
__device__ int    g_coff[NCL+1];
__device__ int    g_dst[NIT];
__device__ __align__(16) unsigned short g_Hh[NB*DD];
__device__ __align__(16) unsigned short g_Hl[NB*DD];
__device__ __align__(16) unsigned short g_W2h[(size_t)NP*DD];   // padding rows stay 0 forever

// ---------------- PTX helpers (sm_80-class baseline ISA) --------------------
__device__ __forceinline__ uint32_t smem_u32(const void* p) {
    uint32_t a;
    asm("{ .reg .u64 t; cvta.to.shared.u64 t, %1; cvt.u32.u64 %0, t; }" : "=r"(a) : "l"(p));
    return a;
}
__device__ __forceinline__ float ex2f(float x) {
    float r; asm("ex2.approx.ftz.f32 %0, %1;" : "=f"(r) : "f"(x)); return r;
}
#define SW128(o) ((o) ^ (((o) >> 3) & 0x70))

__device__ __forceinline__ void cpa16(uint32_t dst, const void* src) {
    asm volatile("cp.async.cg.shared.global [%0], [%1], 16;" :: "r"(dst), "l"(src));
}
#define CPA_COMMIT() asm volatile("cp.async.commit_group;")
#define CPA_WAIT0()  asm volatile("cp.async.wait_group 0;" ::: "memory")
#define CPA_WAIT1()  asm volatile("cp.async.wait_group 1;" ::: "memory")

#define LDSM4(R, A) \
    asm volatile("ldmatrix.sync.aligned.m8n8.x4.shared.b16 {%0,%1,%2,%3}, [%4];" \
        : "=r"((R)[0]), "=r"((R)[1]), "=r"((R)[2]), "=r"((R)[3]) : "r"(A))

__device__ __forceinline__ void mma_bf16(float* c, const uint* a, uint b0, uint b1) {
    asm volatile("mma.sync.aligned.m16n8k16.row.col.f32.bf16.bf16.f32 "
        "{%0,%1,%2,%3}, {%4,%5,%6,%7}, {%8,%9}, {%0,%1,%2,%3};"
        : "+f"(c[0]), "+f"(c[1]), "+f"(c[2]), "+f"(c[3])
        : "r"(a[0]), "r"(a[1]), "r"(a[2]), "r"(a[3]), "r"(b0), "r"(b1));
}

// ===========================================================================
// Kernel 1: kpre = histogram (blocks 0..97) + G1 segment-sum (blocks 98..225)
// g_G1 / g_hist: g_G1 is zero on entry (initial load or kfin of previous run).
// ===========================================================================
__global__ void kpre(const int* __restrict__ cl, const float* __restrict__ W1) {
    int t = threadIdx.x;
    if (blockIdx.x < NSC) {
        // ---- histogram ----
        __shared__ int h[NCL];
        if (t < NCL) h[t] = 0;
        __syncthreads();
        int base = blockIdx.x * SSPAN;
        int cnt[NCL];
#pragma unroll
        for (int k = 0; k < NCL; k++) cnt[k] = 0;
#pragma unroll
        for (int q = 0; q < 4; q++) {
            int i = base + q*256 + t;
            if (i < NIT) {
                int c = cl[i];
#pragma unroll
                for (int k = 0; k < NCL; k++) if (c == k) cnt[k]++;
            }
        }
#pragma unroll
        for (int k = 0; k < NCL; k++) if (cnt[k]) atomicAdd(&h[k], cnt[k]);
        __syncthreads();
        if (t < NCL) g_hist[blockIdx.x*NCL + t] = h[t];
    } else {
        // ---- G1 = segment-sum of W1 ----
        int d = t & 63;
        int stripe = (blockIdx.x - NSC)*4 + (t >> 6), ns = 128*4;
        float acc[NCL];
#pragma unroll
        for (int k = 0; k < NCL; k++) acc[k] = 0.0f;
        for (int i = stripe; i < NIT; i += ns) {
            int c = cl[i];
            float w = W1[i*DD + d];
#pragma unroll
            for (int k = 0; k < NCL; k++) if (c == k) acc[k] += w;
        }
#pragma unroll
        for (int k = 0; k < NCL; k++) atomicAdd(&g_G1[k*DD + d], acc[k]);
    }
}

// ===========================================================================
// Kernel 2: kscat = inline scan (per-block prefix from g_hist) + rank/scatter
// 320 threads: warps 0..9 do the scan (warp per cluster); scatter uses t<256.
// ===========================================================================
__global__ void kscat(const int* __restrict__ cl) {
    __shared__ int run[NCL];
    __shared__ int wc[8][NCL];
    __shared__ int tot_s[NCL], pre_s[NCL];
    int t = threadIdx.x, lane = t & 31, w = t >> 5;
    int bid = blockIdx.x;

    if (w < NCL) {
        int c = w, full = 0, pre = 0;
        for (int b = lane; b < NSC; b += 32) {
            int v = g_hist[b*NCL + c];
            full += v;
            if (b < bid) pre += v;
        }
#pragma unroll
        for (int o = 16; o; o >>= 1) {
            full += __shfl_xor_sync(~0u, full, o);
            pre  += __shfl_xor_sync(~0u, pre,  o);
        }
        if (!lane) { tot_s[c] = full; pre_s[c] = pre; }
    }
    __syncthreads();
    if (t == 0) {
        int r = 0;
        for (int k = 0; k < NCL; k++) {
            int o = r; r += tot_s[k];
            run[k] = o + pre_s[k];
            if (bid == 0) { g_coff[k] = o; g_cntf[k] = (float)tot_s[k]; }
        }
        if (bid == 0) g_coff[NCL] = r;
    }
    __syncthreads();

    unsigned ltm = (1u << lane) - 1u;
    int base = bid * SSPAN;
    for (int q = 0; q < 4; q++) {
        int i = base + q*256 + t;
        int c = (t < 256 && i < NIT) ? cl[i] : -1;
        int myrank = 0;
#pragma unroll
        for (int k = 0; k < NCL; k++) {
            unsigned b = __ballot_sync(0xffffffffu, c == k);
            if (c == k) myrank = __popc(b & ltm);
            if (w < 8 && lane == 0) wc[w][k] = __popc(b);
        }
        __syncthreads();
        if (t < NCL) {
            int k = t, s = run[k];
            for (int ww = 0; ww < 8; ww++) { int tmp = wc[ww][k]; wc[ww][k] = s; s += tmp; }
            run[k] = s;
        }
        __syncthreads();
        if (c >= 0) g_dst[i] = wc[w][c] + myrank;
        __syncthreads();
    }
}

// ===========================================================================
// Kernel 3: kpermH = W2 permute/transpose/bf16 (blocks 0..390)
//                    + H = (input@G1)*log2e split-bf16 (blocks 391..646)
// ===========================================================================
#define PITCH 264
#define PERMB 391
__global__ void kpermH(const float* __restrict__ W2, const float* __restrict__ inp) {
    int t = threadIdx.x;
    if (blockIdx.x < PERMB) {
        extern __shared__ unsigned short shh[];
        int i = blockIdx.x * 256 + t;
#pragma unroll 8
        for (int d = 0; d < DD; d++) {
            float x = (i < NIT) ? W2[(size_t)d*NIT + i] : 0.0f;
            shh[d*PITCH + t] = __bfloat16_as_ushort(__float2bfloat16(x));
        }
        __syncthreads();
        if (i >= NIT) return;
        int dp = g_dst[i];
        uint v[32];
#pragma unroll
        for (int j = 0; j < 32; j++)
            v[j] = (uint)shh[(2*j)*PITCH + t] | ((uint)shh[(2*j+1)*PITCH + t] << 16);
        uint4* dh = (uint4*)(g_W2h + (size_t)dp*DD);
#pragma unroll
        for (int q = 0; q < 8; q++) dh[q] = make_uint4(v[4*q], v[4*q+1], v[4*q+2], v[4*q+3]);
    } else {
        int e = (blockIdx.x - PERMB) * 256 + t;   // 0..65535
        int b = e >> 6, d = e & 63;
        float a = 0.0f;
#pragma unroll
        for (int c = 0; c < NCL; c++) a += inp[b*NCL + c] * g_G1[c*DD + d];
        a *= LOG2E;
        __nv_bfloat16 h = __float2bfloat16(a);
        float rem = a - __bfloat162float(h);
        g_Hh[b*DD + d] = __bfloat16_as_ushort(h);
        g_Hl[b*DD + d] = __bfloat16_as_ushort(__float2bfloat16(rem));
    }
}

// ===========================================================================
// Kernel 4: kmain — HMMA GEMM (2 passes: Ah*B + Al*B) + exp2/segment epilogue
// ===========================================================================
__device__ __forceinline__ void stage_B(uint32_t sb, int buf, int ch, int t) {
    uint32_t bh = sb + SM_B0 + buf*16384;
    const char* gh = (const char*)g_W2h + (size_t)ch*CH*128;
#pragma unroll
    for (int q = 0; q < 4; q++) {
        int off = (t + q*256) * 16;
        cpa16(bh + SW128(off), gh + off);
    }
}

__global__ void __launch_bounds__(256, 1) kmain() {
    extern __shared__ char dsm[];
    __shared__ int coff_s[NCL+1];
    uint32_t sb = (smem_u32(dsm) + 1023u) & ~1023u;

    int t = threadIdx.x, lane = t & 31, w = t >> 5;
    int bbase = blockIdx.x * BT;
    int ch_lo = blockIdx.y * CPS;
    int ch_hi = min(ch_lo + CPS, NCH);
    int n = ch_hi - ch_lo;

    if (t < NCL+1) coff_s[t] = g_coff[t];

    // stage A (Hh/Hl, SW128) + first B chunk
    {
        const char* gh = (const char*)g_Hh + (size_t)bbase*128;
        const char* gl = (const char*)g_Hl + (size_t)bbase*128;
#pragma unroll
        for (int q = 0; q < 4; q++) {
            int off = (t + q*256) * 16;
            int so  = SW128(off);
            cpa16(sb + SM_AH + so, gh + off);
            cpa16(sb + SM_AL + so, gl + off);
        }
    }
    stage_B(sb, 0, ch_lo, t);
    CPA_COMMIT();
    CPA_WAIT0();
    __syncthreads();

    // per-lane ldmatrix B address precompute
    int m  = lane >> 3, rl = lane & 7;
    int rowb = ((m >> 1) << 3) + rl;
    int kadd = m & 1;
    int bx[4];
#pragma unroll
    for (int ks = 0; ks < 4; ks++)
        bx[ks] = rowb*128 + ((ks*32 + kadd*16) ^ (rl*16));

    // A fragments resident in registers for the whole kernel
    uint ah[4][4], al[4][4];
    {
        int arow = w*16 + ((lane >> 3) & 1)*8 + rl;
#pragma unroll
        for (int ks = 0; ks < 4; ks++) {
            int au   = ks*2 + (lane >> 4);
            int aoff = arow*128 + ((au*16) ^ (rl*16));
            LDSM4(ah[ks], sb + SM_AH + aoff);
            LDSM4(al[ks], sb + SM_AL + aoff);
        }
    }

    int row0 = bbase + w*16 + (lane >> 2);
    int row1 = row0 + 8;
    int qd   = (lane & 3) * 2;
    float s0a = 0.f, s0b = 0.f, s1a = 0.f, s1b = 0.f;
    int cur = 0;
    { int ib = ch_lo * CH; while (coff_s[cur+1] <= ib) cur++; }

    for (int ii = 0; ii < n; ii++) {
        int buf = ii & 1;
        if (ii + 1 < n) { stage_B(sb, buf ^ 1, ch_lo + ii + 1, t); CPA_COMMIT(); CPA_WAIT1(); }
        else            { CPA_WAIT0(); }
        __syncthreads();

        uint32_t bbh = sb + SM_B0 + buf*16384;

        float acc[16][4];
#pragma unroll
        for (int nt = 0; nt < 16; nt++)
#pragma unroll
            for (int j = 0; j < 4; j++) acc[nt][j] = 0.0f;

        // ks outer, ntp inner -> consecutive MMAs hit different accumulators
#pragma unroll
        for (int ks = 0; ks < 4; ks++) {
#pragma unroll
            for (int ntp = 0; ntp < 8; ntp++) {
                uint r[4];
                LDSM4(r, bbh + ntp*2048 + bx[ks]);
                mma_bf16(acc[2*ntp],   ah[ks], r[0], r[1]);
                mma_bf16(acc[2*ntp+1], ah[ks], r[2], r[3]);
                mma_bf16(acc[2*ntp],   al[ks], r[0], r[1]);
                mma_bf16(acc[2*ntp+1], al[ks], r[2], r[3]);
            }
        }

        // epilogue: exp2 + sorted 2-slot segment accumulate
        int ibase = (ch_lo + ii) * CH;
        {
            int nc = cur;
            while (coff_s[nc+1] <= ibase) nc++;
            if (nc != cur) {
                atomicAdd(&g_sums[row0*NCL + cur], s0a);
                atomicAdd(&g_sums[row1*NCL + cur], s0b);
                if (cur + 1 < NCL) {
                    atomicAdd(&g_sums[row0*NCL + cur + 1], s1a);
                    atomicAdd(&g_sums[row1*NCL + cur + 1], s1b);
                }
                s0a = s0b = s1a = s1b = 0.f;
                cur = nc;
            }
        }
        int bpos = coff_s[cur+1];

#pragma unroll
        for (int nt = 0; nt < 16; nt++) {
            float e0 = ex2f(acc[nt][0]);
            float e1 = ex2f(acc[nt][1]);
            float e2 = ex2f(acc[nt][2]);
            float e3 = ex2f(acc[nt][3]);
            int p0 = ibase + nt*8 + qd;
            if (p0 < bpos)          { s0a += e0; s0b += e2; }
            else if (p0 < NIT)      { s1a += e0; s1b += e2; }
            if (p0 + 1 < bpos)      { s0a += e1; s0b += e3; }
            else if (p0 + 1 < NIT)  { s1a += e1; s1b += e3; }
        }
        __syncthreads();
    }

    atomicAdd(&g_sums[row0*NCL + cur], s0a);
    atomicAdd(&g_sums[row1*NCL + cur], s0b);
    if (cur + 1 < NCL) {
        atomicAdd(&g_sums[row0*NCL + cur + 1], s1a);
        atomicAdd(&g_sums[row1*NCL + cur + 1], s1b);
    }
}

// ===========================================================================
// Kernel 5: kfin — finalize output AND restore scratch zeros for next run
// ===========================================================================
__global__ void kfin(float* __restrict__ out) {
    int t = threadIdx.x;
    int b = blockIdx.x * 256 + t;
    if (b < NB) {
        float v[NCL], z = 0.0f;
#pragma unroll
        for (int c = 0; c < NCL; c++) { v[c] = g_sums[b*NCL + c]; z += v[c]; }
        float invz = 1.0f / z;
#pragma unroll
        for (int c = 0; c < NCL; c++)
            out[b*NCL + c] = v[c] * invz / fmaxf(g_cntf[c], 1.0f);
        // restore zeros (each thread owns its row; no races)
#pragma unroll
        for (int c = 0; c < NCL; c++) g_sums[b*NCL + c] = 0.0f;
    }
    if (blockIdx.x == 0) {
        for (int i = t; i < NCL*DD; i += 256) g_G1[i] = 0.0f;
    }
}

// ---------------------------------------------------------------------------
extern "C" void kernel_launch(void* const* d_in, const int* in_sizes, int n_in,
                              void* d_out, int out_size) {
    const float* input = (const float*)d_in[0];   // (1024, 10) f32
    const int*   clust = (const int*)d_in[1];     // (100000,) i32
    const float* W1    = (const float*)d_in[2];   // (100000, 64) f32
    const float* W2    = (const float*)d_in[3];   // (64, 100000) f32
    float*       out   = (float*)d_out;           // (1024, 10) f32

    cudaFuncSetAttribute(kmain, cudaFuncAttributeMaxDynamicSharedMemorySize, SMEM_KM);
    cudaFuncSetAttribute(kpermH, cudaFuncAttributeMaxDynamicSharedMemorySize, DD*PITCH*2);

    kpre<<<NSC + 128, 256>>>(clust, W1);
    kscat<<<NSC, 320>>>(clust);
    kpermH<<<PERMB + 256, 256, DD*PITCH*2>>>(W2, input);
    dim3 grid(NB / BT, NS);
    kmain<<<grid, 256, SMEM_KM>>>();
    kfin<<<4, 256>>>(out);
}

// round 6
// speedup vs baseline: 5.2315x; 1.4056x over previous
#include <cuda_runtime.h>
#include <cuda_bf16.h>
#include <cstdint>

typedef unsigned int uint;

#define NB      1024
#define NIT     100000
#define NCL     10
#define DD      64
#define CH      128                  // items per chunk
#define NCH     782                  // NP / CH
#define NP      (NCH*CH)             // 100096
#define NS      36                   // item splits
#define CPS     22                   // chunks per CTA (ceil 782/36)
#define BT      128                  // batch rows per CTA
#define NSC     98                   // sort CTAs
#define SSPAN   1024
#define LOG2E   1.4426950408889634f

// kmain smem (relative to 1024-aligned base): Ah@0 (16K) | B0@16K B1@32K
#define SM_AH   0
#define SM_B0   16384
#define SMEM_KM (49152 + 1024)

// ---------------- device scratch (zero at load; kfin restores zeros) -------
__device__ float  g_G1[NCL*DD];
__device__ float  g_sums[NB*NCL];
__device__ float  g_cntf[NCL];
__device__ int    g_hist[NSC*NCL];
__device__ int    g_coff[NCL+1];
__device__ int    g_dst[NIT];
__device__ __align__(16) unsigned short g_Hh[NB*DD];
__device__ __align__(16) unsigned short g_W2h[(size_t)NP*DD];   // padding rows stay 0 forever

// ---------------- PTX helpers (sm_80-class baseline ISA) --------------------
__device__ __forceinline__ uint32_t smem_u32(const void* p) {
    uint32_t a;
    asm("{ .reg .u64 t; cvta.to.shared.u64 t, %1; cvt.u32.u64 %0, t; }" : "=r"(a) : "l"(p));
    return a;
}
__device__ __forceinline__ float ex2f(float x) {
    float r; asm("ex2.approx.ftz.f32 %0, %1;" : "=f"(r) : "f"(x)); return r;
}
#define SW128(o) ((o) ^ (((o) >> 3) & 0x70))

__device__ __forceinline__ void cpa16(uint32_t dst, const void* src) {
    asm volatile("cp.async.cg.shared.global [%0], [%1], 16;" :: "r"(dst), "l"(src));
}
#define CPA_COMMIT() asm volatile("cp.async.commit_group;")
#define CPA_WAIT0()  asm volatile("cp.async.wait_group 0;" ::: "memory")
#define CPA_WAIT1()  asm volatile("cp.async.wait_group 1;" ::: "memory")

#define LDSM4(R, A) \
    asm volatile("ldmatrix.sync.aligned.m8n8.x4.shared.b16 {%0,%1,%2,%3}, [%4];" \
        : "=r"((R)[0]), "=r"((R)[1]), "=r"((R)[2]), "=r"((R)[3]) : "r"(A))

__device__ __forceinline__ void mma_bf16(float* c, const uint* a, uint b0, uint b1) {
    asm volatile("mma.sync.aligned.m16n8k16.row.col.f32.bf16.bf16.f32 "
        "{%0,%1,%2,%3}, {%4,%5,%6,%7}, {%8,%9}, {%0,%1,%2,%3};"
        : "+f"(c[0]), "+f"(c[1]), "+f"(c[2]), "+f"(c[3])
        : "r"(a[0]), "r"(a[1]), "r"(a[2]), "r"(a[3]), "r"(b0), "r"(b1));
}

// ===========================================================================
// Kernel 1: kpre = histogram (blocks 0..97) + G1 segment-sum (blocks 98..353)
// ===========================================================================
__global__ void kpre(const int* __restrict__ cl, const float* __restrict__ W1) {
    int t = threadIdx.x;
    if (blockIdx.x < NSC) {
        __shared__ int h[NCL];
        if (t < NCL) h[t] = 0;
        __syncthreads();
        int base = blockIdx.x * SSPAN;
        int cnt[NCL];
#pragma unroll
        for (int k = 0; k < NCL; k++) cnt[k] = 0;
#pragma unroll
        for (int q = 0; q < 4; q++) {
            int i = base + q*256 + t;
            if (i < NIT) {
                int c = cl[i];
#pragma unroll
                for (int k = 0; k < NCL; k++) if (c == k) cnt[k]++;
            }
        }
#pragma unroll
        for (int k = 0; k < NCL; k++) if (cnt[k]) atomicAdd(&h[k], cnt[k]);
        __syncthreads();
        if (t < NCL) g_hist[blockIdx.x*NCL + t] = h[t];
    } else {
        int d = t & 63;
        int stripe = (blockIdx.x - NSC)*4 + (t >> 6), ns = 256*4;
        float acc[NCL];
#pragma unroll
        for (int k = 0; k < NCL; k++) acc[k] = 0.0f;
        for (int i = stripe; i < NIT; i += ns) {
            int c = cl[i];
            float w = W1[i*DD + d];
#pragma unroll
            for (int k = 0; k < NCL; k++) if (c == k) acc[k] += w;
        }
#pragma unroll
        for (int k = 0; k < NCL; k++) atomicAdd(&g_G1[k*DD + d], acc[k]);
    }
}

// ===========================================================================
// Kernel 2: kscat = inline scan + match-based rank/scatter (deterministic)
// 320 threads: warps 0..9 scan (warp per cluster); scatter uses t<256.
// ===========================================================================
__global__ void kscat(const int* __restrict__ cl) {
    __shared__ int run[NCL];
    __shared__ int wc[8][NCL];
    __shared__ int tot_s[NCL], pre_s[NCL];
    int t = threadIdx.x, lane = t & 31, w = t >> 5;
    int bid = blockIdx.x;

    if (w < NCL) {
        int c = w, full = 0, pre = 0;
        for (int b = lane; b < NSC; b += 32) {
            int v = g_hist[b*NCL + c];
            full += v;
            if (b < bid) pre += v;
        }
#pragma unroll
        for (int o = 16; o; o >>= 1) {
            full += __shfl_xor_sync(~0u, full, o);
            pre  += __shfl_xor_sync(~0u, pre,  o);
        }
        if (!lane) { tot_s[c] = full; pre_s[c] = pre; }
    }
    __syncthreads();
    if (t == 0) {
        int r = 0;
        for (int k = 0; k < NCL; k++) {
            int o = r; r += tot_s[k];
            run[k] = o + pre_s[k];
            if (bid == 0) { g_coff[k] = o; g_cntf[k] = (float)tot_s[k]; }
        }
        if (bid == 0) g_coff[NCL] = r;
    }
    __syncthreads();

    unsigned ltm = (1u << lane) - 1u;
    int base = bid * SSPAN;
    for (int q = 0; q < 4; q++) {
        if (t < 80) ((int*)wc)[t] = 0;
        __syncthreads();
        int i = base + q*256 + t;
        int c = (t < 256 && i < NIT) ? cl[i] : -1;
        unsigned mm = __match_any_sync(0xffffffffu, c);
        int myrank = __popc(mm & ltm);
        if (c >= 0 && myrank == 0) wc[w][c] = __popc(mm);
        __syncthreads();
        if (t < NCL) {
            int k = t, s = run[k];
            for (int ww = 0; ww < 8; ww++) { int tmp = wc[ww][k]; wc[ww][k] = s; s += tmp; }
            run[k] = s;
        }
        __syncthreads();
        if (c >= 0) g_dst[i] = wc[w][c] + myrank;
        __syncthreads();
    }
}

// ===========================================================================
// Kernel 3: kpermH = W2 permute/transpose/bf16 (blocks 0..390)
//                    + Hh = bf16((input@G1)*log2e) (blocks 391..646)
// ===========================================================================
#define PITCH 264
#define PERMB 391
__global__ void kpermH(const float* __restrict__ W2, const float* __restrict__ inp) {
    int t = threadIdx.x;
    if (blockIdx.x < PERMB) {
        extern __shared__ unsigned short shh[];
        int i = blockIdx.x * 256 + t;
#pragma unroll 8
        for (int d = 0; d < DD; d++) {
            float x = (i < NIT) ? W2[(size_t)d*NIT + i] : 0.0f;
            shh[d*PITCH + t] = __bfloat16_as_ushort(__float2bfloat16(x));
        }
        __syncthreads();
        if (i >= NIT) return;
        int dp = g_dst[i];
        uint v[32];
#pragma unroll
        for (int j = 0; j < 32; j++)
            v[j] = (uint)shh[(2*j)*PITCH + t] | ((uint)shh[(2*j+1)*PITCH + t] << 16);
        uint4* dh = (uint4*)(g_W2h + (size_t)dp*DD);
#pragma unroll
        for (int q = 0; q < 8; q++) dh[q] = make_uint4(v[4*q], v[4*q+1], v[4*q+2], v[4*q+3]);
    } else {
        int e = (blockIdx.x - PERMB) * 256 + t;   // 0..65535
        int b = e >> 6, d = e & 63;
        float a = 0.0f;
#pragma unroll
        for (int c = 0; c < NCL; c++) a += inp[b*NCL + c] * g_G1[c*DD + d];
        g_Hh[b*DD + d] = __bfloat16_as_ushort(__float2bfloat16(a * LOG2E));
    }
}

// ===========================================================================
// Kernel 4: kmain — single-pass bf16 HMMA GEMM + exp2/segment epilogue
// ===========================================================================
__device__ __forceinline__ void stage_B(uint32_t sb, int buf, int ch, int t) {
    uint32_t bh = sb + SM_B0 + buf*16384;
    const char* gh = (const char*)g_W2h + (size_t)ch*CH*128;
#pragma unroll
    for (int q = 0; q < 4; q++) {
        int off = (t + q*256) * 16;
        cpa16(bh + SW128(off), gh + off);
    }
}

__global__ void __launch_bounds__(256, 2) kmain() {
    extern __shared__ char dsm[];
    __shared__ int coff_s[NCL+1];
    uint32_t sb = (smem_u32(dsm) + 1023u) & ~1023u;

    int t = threadIdx.x, lane = t & 31, w = t >> 5;
    int bbase = blockIdx.x * BT;
    int ch_lo = blockIdx.y * CPS;
    int ch_hi = min(ch_lo + CPS, NCH);
    int n = ch_hi - ch_lo;

    if (t < NCL+1) coff_s[t] = g_coff[t];

    // stage A (Hh, 16 KB, SW128) + first B chunk
    {
        const char* gh = (const char*)g_Hh + (size_t)bbase*128;
#pragma unroll
        for (int q = 0; q < 4; q++) {
            int off = (t + q*256) * 16;
            cpa16(sb + SM_AH + SW128(off), gh + off);
        }
    }
    stage_B(sb, 0, ch_lo, t);
    CPA_COMMIT();
    CPA_WAIT0();
    __syncthreads();

    // per-lane ldmatrix B address precompute
    int m  = lane >> 3, rl = lane & 7;
    int rowb = ((m >> 1) << 3) + rl;
    int kadd = m & 1;
    int bx[4];
#pragma unroll
    for (int ks = 0; ks < 4; ks++)
        bx[ks] = rowb*128 + ((ks*32 + kadd*16) ^ (rl*16));

    // A fragments resident in registers for the whole kernel
    uint ah[4][4];
    {
        int arow = w*16 + ((lane >> 3) & 1)*8 + rl;
#pragma unroll
        for (int ks = 0; ks < 4; ks++) {
            int au   = ks*2 + (lane >> 4);
            int aoff = arow*128 + ((au*16) ^ (rl*16));
            LDSM4(ah[ks], sb + SM_AH + aoff);
        }
    }

    int row0 = bbase + w*16 + (lane >> 2);
    int row1 = row0 + 8;
    int qd   = (lane & 3) * 2;
    float s0a = 0.f, s0b = 0.f, s1a = 0.f, s1b = 0.f;
    int cur = 0;
    { int ib = ch_lo * CH; while (coff_s[cur+1] <= ib) cur++; }

    for (int ii = 0; ii < n; ii++) {
        int buf = ii & 1;
        if (ii + 1 < n) { stage_B(sb, buf ^ 1, ch_lo + ii + 1, t); CPA_COMMIT(); CPA_WAIT1(); }
        else            { CPA_WAIT0(); }
        __syncthreads();

        uint32_t bbh = sb + SM_B0 + buf*16384;

        float acc[16][4];
#pragma unroll
        for (int nt = 0; nt < 16; nt++)
#pragma unroll
            for (int j = 0; j < 4; j++) acc[nt][j] = 0.0f;

#pragma unroll
        for (int ks = 0; ks < 4; ks++) {
#pragma unroll
            for (int ntp = 0; ntp < 8; ntp++) {
                uint r[4];
                LDSM4(r, bbh + ntp*2048 + bx[ks]);
                mma_bf16(acc[2*ntp],   ah[ks], r[0], r[1]);
                mma_bf16(acc[2*ntp+1], ah[ks], r[2], r[3]);
            }
        }

        // epilogue: exp2 + sorted 2-slot segment accumulate
        int ibase = (ch_lo + ii) * CH;
        {
            int nc = cur;
            while (coff_s[nc+1] <= ibase) nc++;
            if (nc != cur) {
                atomicAdd(&g_sums[row0*NCL + cur], s0a);
                atomicAdd(&g_sums[row1*NCL + cur], s0b);
                if (cur + 1 < NCL) {
                    atomicAdd(&g_sums[row0*NCL + cur + 1], s1a);
                    atomicAdd(&g_sums[row1*NCL + cur + 1], s1b);
                }
                s0a = s0b = s1a = s1b = 0.f;
                cur = nc;
            }
        }
        int bpos = coff_s[cur+1];

#pragma unroll
        for (int nt = 0; nt < 16; nt++) {
            float e0 = ex2f(acc[nt][0]);
            float e1 = ex2f(acc[nt][1]);
            float e2 = ex2f(acc[nt][2]);
            float e3 = ex2f(acc[nt][3]);
            int p0 = ibase + nt*8 + qd;
            if (p0 < bpos)          { s0a += e0; s0b += e2; }
            else if (p0 < NIT)      { s1a += e0; s1b += e2; }
            if (p0 + 1 < bpos)      { s0a += e1; s0b += e3; }
            else if (p0 + 1 < NIT)  { s1a += e1; s1b += e3; }
        }
        __syncthreads();
    }

    atomicAdd(&g_sums[row0*NCL + cur], s0a);
    atomicAdd(&g_sums[row1*NCL + cur], s0b);
    if (cur + 1 < NCL) {
        atomicAdd(&g_sums[row0*NCL + cur + 1], s1a);
        atomicAdd(&g_sums[row1*NCL + cur + 1], s1b);
    }
}

// ===========================================================================
// Kernel 5: kfin — finalize output AND restore scratch zeros for next run
// ===========================================================================
__global__ void kfin(float* __restrict__ out) {
    int t = threadIdx.x;
    int b = blockIdx.x * 256 + t;
    if (b < NB) {
        float v[NCL], z = 0.0f;
#pragma unroll
        for (int c = 0; c < NCL; c++) { v[c] = g_sums[b*NCL + c]; z += v[c]; }
        float invz = 1.0f / z;
#pragma unroll
        for (int c = 0; c < NCL; c++)
            out[b*NCL + c] = v[c] * invz / fmaxf(g_cntf[c], 1.0f);
#pragma unroll
        for (int c = 0; c < NCL; c++) g_sums[b*NCL + c] = 0.0f;
    }
    if (blockIdx.x == 0) {
        for (int i = t; i < NCL*DD; i += 256) g_G1[i] = 0.0f;
    }
}

// ---------------------------------------------------------------------------
extern "C" void kernel_launch(void* const* d_in, const int* in_sizes, int n_in,
                              void* d_out, int out_size) {
    const float* input = (const float*)d_in[0];   // (1024, 10) f32
    const int*   clust = (const int*)d_in[1];     // (100000,) i32
    const float* W1    = (const float*)d_in[2];   // (100000, 64) f32
    const float* W2    = (const float*)d_in[3];   // (64, 100000) f32
    float*       out   = (float*)d_out;           // (1024, 10) f32

    cudaFuncSetAttribute(kmain, cudaFuncAttributeMaxDynamicSharedMemorySize, SMEM_KM);
    cudaFuncSetAttribute(kpermH, cudaFuncAttributeMaxDynamicSharedMemorySize, DD*PITCH*2);

    kpre<<<NSC + 256, 256>>>(clust, W1);
    kscat<<<NSC, 320>>>(clust);
    kpermH<<<PERMB + 256, 256, DD*PITCH*2>>>(W2, input);
    dim3 grid(NB / BT, NS);
    kmain<<<grid, 256, SMEM_KM>>>();
    kfin<<<4, 256>>>(out);
}